// round 15
// baseline (speedup 1.0000x reference)
#include <cuda_runtime.h>
#include <cuda_bf16.h>
#include <cstdint>

#define NN  50000
#define EE  800000
#define RR  8
#define FIN 128
#define HH1 64
#define HH2 128
#define BB  64
#define NSEG (NN * RR)

// ---------------- device-global scratch ------------------------------------
__device__ __align__(16) float g_big[(size_t)NN * 512];  // h1 [n][8*64] fp32
__device__ __align__(16) float g_s2 [(size_t)NN * 512];  // S2 [n][8*64]
__device__ __align__(16) float g_x1[(size_t)NN * HH1];
__device__ __align__(16) float g_h2[(size_t)NN * HH2];
__device__ int   g_cnt[NSEG];
__device__ float g_psum[BB * HH2];
__device__ int   g_pmax[BB * HH2];
__device__ float g_pcnt[BB];
__device__ __align__(16) unsigned short Wb1h[9 * 64 * 128];   // [r][n][k]
__device__ __align__(16) unsigned short Wb1l[9 * 64 * 128];
__device__ __align__(16) unsigned short Wb2h[128 * 576];      // [n][k]
__device__ __align__(16) unsigned short Wb2l[128 * 576];

// ---------------- mma helpers ----------------
__device__ __forceinline__ uint32_t smem_u32(const void* p) {
    uint32_t a;
    asm("{ .reg .u64 t; cvta.to.shared.u64 t, %1; cvt.u32.u64 %0, t; }" : "=r"(a) : "l"(p));
    return a;
}
__device__ __forceinline__ void ldm_x4(uint32_t* r, uint32_t addr) {
    asm volatile("ldmatrix.sync.aligned.m8n8.x4.shared.b16 {%0,%1,%2,%3}, [%4];"
                 : "=r"(r[0]), "=r"(r[1]), "=r"(r[2]), "=r"(r[3]) : "r"(addr));
}
__device__ __forceinline__ void mma_bf16(float* c, const uint32_t* a, uint32_t b0, uint32_t b1) {
    asm volatile("mma.sync.aligned.m16n8k16.row.col.f32.bf16.bf16.f32 "
                 "{%0,%1,%2,%3}, {%4,%5,%6,%7}, {%8,%9}, {%0,%1,%2,%3};"
                 : "+f"(c[0]), "+f"(c[1]), "+f"(c[2]), "+f"(c[3])
                 : "r"(a[0]), "r"(a[1]), "r"(a[2]), "r"(a[3]), "r"(b0), "r"(b1));
}
__device__ __forceinline__ uint32_t pack_hi(float a, float b, uint32_t& lo) {
    __nv_bfloat16 ha = __float2bfloat16_rn(a), hb = __float2bfloat16_rn(b);
    __nv_bfloat16 la = __float2bfloat16_rn(a - __bfloat162float(ha));
    __nv_bfloat16 lb = __float2bfloat16_rn(b - __bfloat162float(hb));
    lo = (uint32_t)__bfloat16_as_ushort(la) | ((uint32_t)__bfloat16_as_ushort(lb) << 16);
    return (uint32_t)__bfloat16_as_ushort(ha) | ((uint32_t)__bfloat16_as_ushort(hb) << 16);
}

// ---------------- degree count + weight prep --------------------------------
#define PREP1_N (9 * 64 * 128)
#define PREP2_N (128 * 576)
__global__ void k_count(const int* __restrict__ dst, const int* __restrict__ et) {
    int e = blockIdx.x * blockDim.x + threadIdx.x;
    if (e < EE) atomicAdd(&g_cnt[dst[e] * RR + et[e]], 1);
}
__global__ void k_prep1(const float* __restrict__ W1, const float* __restrict__ root1) {
    int i = blockIdx.x * blockDim.x + threadIdx.x;
    if (i >= PREP1_N) return;
    int r = i >> 13, rem = i & 8191, n = rem >> 7, k = rem & 127;
    float v = (r < 8) ? W1[((size_t)r * 128 + k) * 64 + n] : root1[(size_t)k * 64 + n];
    __nv_bfloat16 h = __float2bfloat16_rn(v);
    Wb1h[i] = __bfloat16_as_ushort(h);
    Wb1l[i] = __bfloat16_as_ushort(__float2bfloat16_rn(v - __bfloat162float(h)));
}
__global__ void k_prep2(const float* __restrict__ W2, const float* __restrict__ root2) {
    int j = blockIdx.x * blockDim.x + threadIdx.x;
    if (j >= PREP2_N) return;
    int n = j / 576, k = j % 576;
    float v = (k < 512) ? W2[(size_t)k * 128 + n] : root2[(size_t)(k - 512) * 128 + n];
    __nv_bfloat16 h = __float2bfloat16_rn(v);
    Wb2h[j] = __bfloat16_as_ushort(h);
    Wb2l[j] = __bfloat16_as_ushort(__float2bfloat16_rn(v - __bfloat162float(h)));
}

// ---------------- layer-1 GEMM: 128 thr, block 128Mx64N, warp 64Mx32N ------
// (round-12 version, measured 77us)
#define G1_AL 32768
#define G1_BH 65536
#define G1_BL 81920
#define G1_TOTAL 98304

__global__ __launch_bounds__(128, 2) void k_gemm1_mma(const float* __restrict__ x,
                                                      const float* __restrict__ b1) {
    extern __shared__ char sm[];
    const int tid = threadIdx.x, lane = tid & 31, w = tid >> 5;
    const int n0 = blockIdx.x * 128;
    const int m_off = (w & 1) * 64;
    const int n_off = (w >> 1) * 32;
    const uint32_t sbase = smem_u32(sm);

    #pragma unroll
    for (int it = 0; it < 16; it++) {
        int idx = tid + it * 128;
        int row = idx >> 4, g = idx & 15;
        int n = n0 + row;
        float v[8];
        if (n < NN) {
            float4 a = *(const float4*)(x + (size_t)n * FIN + g * 8);
            float4 b = *(const float4*)(x + (size_t)n * FIN + g * 8 + 4);
            v[0]=a.x; v[1]=a.y; v[2]=a.z; v[3]=a.w; v[4]=b.x; v[5]=b.y; v[6]=b.z; v[7]=b.w;
        } else {
            #pragma unroll
            for (int j = 0; j < 8; j++) v[j] = 0.0f;
        }
        uint32_t hu[4], lu[4];
        #pragma unroll
        for (int m = 0; m < 4; m++) hu[m] = pack_hi(v[2*m], v[2*m+1], lu[m]);
        uint32_t off = row * 256 + ((g * 16) ^ ((row & 7) << 4));
        *(uint4*)(sm + off)         = make_uint4(hu[0], hu[1], hu[2], hu[3]);
        *(uint4*)(sm + G1_AL + off) = make_uint4(lu[0], lu[1], lu[2], lu[3]);
    }

    for (int r = 0; r < 9; r++) {
        #pragma unroll
        for (int it = 0; it < 8; it++) {
            int idx = tid + it * 128;
            int row = idx >> 4, g = idx & 15;
            uint4 hv = *(const uint4*)(Wb1h + ((size_t)r * 64 + row) * 128 + g * 8);
            uint4 lv = *(const uint4*)(Wb1l + ((size_t)r * 64 + row) * 128 + g * 8);
            uint32_t off = row * 256 + ((g * 16) ^ ((row & 7) << 4));
            *(uint4*)(sm + G1_BH + off) = hv;
            *(uint4*)(sm + G1_BL + off) = lv;
        }
        __syncthreads();

        float acc[4][4][4] = {};
        #pragma unroll
        for (int s = 0; s < 8; s++) {
            uint32_t ah[4][4], al[4][4];
            #pragma unroll
            for (int mt = 0; mt < 4; mt++) {
                int row = m_off + mt * 16 + (lane & 15);
                int kb = s * 32 + (lane >> 4) * 16;
                uint32_t off = row * 256 + (kb ^ ((row & 7) << 4));
                ldm_x4(ah[mt], sbase + off);
                ldm_x4(al[mt], sbase + G1_AL + off);
            }
            #pragma unroll
            for (int ng = 0; ng < 2; ng++) {
                uint32_t bh[4], bl[4];
                int nb = n_off + ng * 16 + (lane & 7) + ((lane >> 4) << 3);
                int kb = s * 32 + ((lane >> 3) & 1) * 16;
                uint32_t off = nb * 256 + (kb ^ ((nb & 7) << 4));
                ldm_x4(bh, sbase + G1_BH + off);
                ldm_x4(bl, sbase + G1_BL + off);
                #pragma unroll
                for (int mt = 0; mt < 4; mt++)
                    #pragma unroll
                    for (int sub = 0; sub < 2; sub++) {
                        float* c = acc[mt][ng * 2 + sub];
                        mma_bf16(c, ah[mt], bh[sub*2], bh[sub*2+1]);
                        mma_bf16(c, al[mt], bh[sub*2], bh[sub*2+1]);
                        mma_bf16(c, ah[mt], bl[sub*2], bl[sub*2+1]);
                    }
            }
        }

        int grow = lane >> 2, gcol = (lane & 3) * 2;
        #pragma unroll
        for (int mt = 0; mt < 4; mt++) {
            int nr0 = n0 + m_off + mt * 16 + grow;
            int nr1 = nr0 + 8;
            #pragma unroll
            for (int nt = 0; nt < 4; nt++) {
                int col = n_off + nt * 8 + gcol;
                float* c = acc[mt][nt];
                if (r < 8) {
                    if (nr0 < NN) *(float2*)&g_big[(size_t)nr0 * 512 + r * 64 + col] = make_float2(c[0], c[1]);
                    if (nr1 < NN) *(float2*)&g_big[(size_t)nr1 * 512 + r * 64 + col] = make_float2(c[2], c[3]);
                } else {
                    float bb0 = b1[col], bb1 = b1[col + 1];
                    if (nr0 < NN) *(float2*)&g_x1[(size_t)nr0 * 64 + col] = make_float2(c[0] + bb0, c[1] + bb1);
                    if (nr1 < NN) *(float2*)&g_x1[(size_t)nr1 * 64 + col] = make_float2(c[2] + bb0, c[3] + bb1);
                }
            }
        }
        __syncthreads();
    }
}

// ---------------- scatters: ILP=8 edges/thread, 16 thr/edge, vector red ----
#define NGRP (EE / 8)   // 100000 edge groups

__global__ __launch_bounds__(256) void k_scatter1(const int* __restrict__ src,
                                                  const int* __restrict__ dst,
                                                  const int* __restrict__ et) {
    long idx = (long)blockIdx.x * blockDim.x + threadIdx.x;
    int grp = (int)(idx >> 4);
    if (grp >= NGRP) return;
    int q = (int)(idx & 15);
    int e0 = grp * 8;
    int s[8], d[8], t[8];
    #pragma unroll
    for (int j = 0; j < 8; j++) { s[j] = src[e0+j]; d[j] = dst[e0+j]; t[j] = et[e0+j]; }
    int c[8];
    #pragma unroll
    for (int j = 0; j < 8; j++) c[j] = g_cnt[d[j] * RR + t[j]];
    float4 v[8];
    #pragma unroll
    for (int j = 0; j < 8; j++)
        v[j] = *(const float4*)&g_big[(size_t)s[j] * 512 + t[j] * 64 + q * 4];
    #pragma unroll
    for (int j = 0; j < 8; j++) {
        float w = 1.0f / (float)(c[j] > 1 ? c[j] : 1);
        float* p = &g_x1[(size_t)d[j] * 64 + q * 4];
        asm volatile("red.global.add.v4.f32 [%0], {%1, %2, %3, %4};"
                     :: "l"(p), "f"(w*v[j].x), "f"(w*v[j].y), "f"(w*v[j].z), "f"(w*v[j].w)
                     : "memory");
    }
}

__global__ __launch_bounds__(256) void k_scatter2(const int* __restrict__ src,
                                                  const int* __restrict__ dst,
                                                  const int* __restrict__ et) {
    long idx = (long)blockIdx.x * blockDim.x + threadIdx.x;
    int grp = (int)(idx >> 4);
    if (grp >= NGRP) return;
    int q = (int)(idx & 15);
    int e0 = grp * 8;
    int s[8], d[8], t[8];
    #pragma unroll
    for (int j = 0; j < 8; j++) { s[j] = src[e0+j]; d[j] = dst[e0+j]; t[j] = et[e0+j]; }
    int c[8];
    #pragma unroll
    for (int j = 0; j < 8; j++) c[j] = g_cnt[d[j] * RR + t[j]];
    float4 v[8];
    #pragma unroll
    for (int j = 0; j < 8; j++)
        v[j] = *(const float4*)&g_x1[(size_t)s[j] * 64 + q * 4];
    #pragma unroll
    for (int j = 0; j < 8; j++) {
        float w = 1.0f / (float)(c[j] > 1 ? c[j] : 1);
        float* p = &g_s2[(size_t)d[j] * 512 + t[j] * 64 + q * 4];
        asm volatile("red.global.add.v4.f32 [%0], {%1, %2, %3, %4};"
                     :: "l"(p), "f"(w*fmaxf(v[j].x,0.f)), "f"(w*fmaxf(v[j].y,0.f)),
                        "f"(w*fmaxf(v[j].z,0.f)), "f"(w*fmaxf(v[j].w,0.f)) : "memory");
    }
}

// ---------------- layer-2 GEMM: 256 thr, block 128Mx128N, warp 64Mx32N -----
// full 255-reg budget (LB 256,1) to avoid round-12's spills
#define G2_AL 16384
#define G2_BH 32768
#define G2_BL 49152
#define G2_TOTAL 65536

__global__ __launch_bounds__(256, 1) void k_gemm2_mma(const float* __restrict__ b2) {
    extern __shared__ char sm[];
    const int tid = threadIdx.x, lane = tid & 31, w = tid >> 5;
    const int n0 = blockIdx.x * 128;
    const int m_off = (w & 1) * 64;
    const int n_off = (w >> 1) * 32;
    const uint32_t sbase = smem_u32(sm);

    float acc[4][4][4] = {};

    for (int c = 0; c < 9; c++) {
        // A chunk: 128 rows x 64 k fp32 -> bf16 hi/lo (relu for the x1 chunk)
        #pragma unroll
        for (int it = 0; it < 4; it++) {
            int idx = tid + it * 256;
            int row = idx >> 3, g = idx & 7;
            int n = n0 + row;
            float v[8];
            if (n < NN) {
                const float* pb = (c < 8) ? &g_s2[(size_t)n * 512 + c * 64 + g * 8]
                                          : &g_x1[(size_t)n * 64 + g * 8];
                float4 a = *(const float4*)pb;
                float4 b = *(const float4*)(pb + 4);
                if (c < 8) {
                    v[0]=a.x; v[1]=a.y; v[2]=a.z; v[3]=a.w; v[4]=b.x; v[5]=b.y; v[6]=b.z; v[7]=b.w;
                } else {
                    v[0]=fmaxf(a.x,0.f); v[1]=fmaxf(a.y,0.f); v[2]=fmaxf(a.z,0.f); v[3]=fmaxf(a.w,0.f);
                    v[4]=fmaxf(b.x,0.f); v[5]=fmaxf(b.y,0.f); v[6]=fmaxf(b.z,0.f); v[7]=fmaxf(b.w,0.f);
                }
            } else {
                #pragma unroll
                for (int j = 0; j < 8; j++) v[j] = 0.0f;
            }
            uint32_t hu[4], lu[4];
            #pragma unroll
            for (int m = 0; m < 4; m++) hu[m] = pack_hi(v[2*m], v[2*m+1], lu[m]);
            uint32_t off = row * 128 + ((g * 16) ^ ((row & 7) << 4));
            *(uint4*)(sm + off)         = make_uint4(hu[0], hu[1], hu[2], hu[3]);
            *(uint4*)(sm + G2_AL + off) = make_uint4(lu[0], lu[1], lu[2], lu[3]);
        }
        // B chunk: 128 n-rows x 64 k bf16 hi/lo
        #pragma unroll
        for (int it = 0; it < 4; it++) {
            int idx = tid + it * 256;
            int row = idx >> 3, g = idx & 7;
            uint4 hv = *(const uint4*)(Wb2h + (size_t)row * 576 + c * 64 + g * 8);
            uint4 lv = *(const uint4*)(Wb2l + (size_t)row * 576 + c * 64 + g * 8);
            uint32_t off = row * 128 + ((g * 16) ^ ((row & 7) << 4));
            *(uint4*)(sm + G2_BH + off) = hv;
            *(uint4*)(sm + G2_BL + off) = lv;
        }
        __syncthreads();

        #pragma unroll
        for (int s = 0; s < 4; s++) {
            uint32_t ah[4][4], al[4][4];
            #pragma unroll
            for (int mt = 0; mt < 4; mt++) {
                int row = m_off + mt * 16 + (lane & 15);
                int kb = s * 32 + (lane >> 4) * 16;
                uint32_t off = row * 128 + (kb ^ ((row & 7) << 4));
                ldm_x4(ah[mt], sbase + off);
                ldm_x4(al[mt], sbase + G2_AL + off);
            }
            #pragma unroll
            for (int ng = 0; ng < 2; ng++) {
                uint32_t bh[4], bl[4];
                int nb = n_off + ng * 16 + (lane & 7) + ((lane >> 4) << 3);
                int kb = s * 32 + ((lane >> 3) & 1) * 16;
                uint32_t off = nb * 128 + (kb ^ ((nb & 7) << 4));
                ldm_x4(bh, sbase + G2_BH + off);
                ldm_x4(bl, sbase + G2_BL + off);
                #pragma unroll
                for (int mt = 0; mt < 4; mt++)
                    #pragma unroll
                    for (int sub = 0; sub < 2; sub++) {
                        float* cc = acc[mt][ng * 2 + sub];
                        mma_bf16(cc, ah[mt], bh[sub*2], bh[sub*2+1]);
                        mma_bf16(cc, al[mt], bh[sub*2], bh[sub*2+1]);
                        mma_bf16(cc, ah[mt], bl[sub*2], bl[sub*2+1]);
                    }
            }
        }
        __syncthreads();
    }

    int grow = lane >> 2, gcol = (lane & 3) * 2;
    #pragma unroll
    for (int mt = 0; mt < 4; mt++) {
        int nr0 = n0 + m_off + mt * 16 + grow;
        int nr1 = nr0 + 8;
        #pragma unroll
        for (int nt = 0; nt < 4; nt++) {
            int col = n_off + nt * 8 + gcol;
            float bb0 = b2[col], bb1 = b2[col + 1];
            float* cc = acc[mt][nt];
            if (nr0 < NN)
                *(float2*)&g_h2[(size_t)nr0 * 128 + col] =
                    make_float2(fmaxf(cc[0] + bb0, 0.f), fmaxf(cc[1] + bb1, 0.f));
            if (nr1 < NN)
                *(float2*)&g_h2[(size_t)nr1 * 128 + col] =
                    make_float2(fmaxf(cc[2] + bb0, 0.f), fmaxf(cc[3] + bb1, 0.f));
        }
    }
}

// ---------------- pooling ----------------
__global__ void k_pool(const int* __restrict__ batch) {
    __shared__ int sbt[32];
    int n0 = blockIdx.x * 32;
    int tid = threadIdx.x;
    if (tid < 32) sbt[tid] = (n0 + tid < NN) ? batch[n0 + tid] : -1;
    __syncthreads();
    int d = tid, bcur = -1, cl = 0;
    float s = 0.f, m = 0.f;
    for (int i = 0; i < 32; i++) {
        int n = n0 + i;
        if (n >= NN) break;
        int b = sbt[i];
        if (b != bcur) {
            if (bcur >= 0) {
                atomicAdd(&g_psum[bcur * HH2 + d], s);
                atomicMax(&g_pmax[bcur * HH2 + d], __float_as_int(m));
                if (d == 0) atomicAdd(&g_pcnt[bcur], (float)cl);
            }
            bcur = b; s = 0.f; m = 0.f; cl = 0;
        }
        float v = g_h2[(size_t)n * HH2 + d];
        s += v; m = fmaxf(m, v); cl++;
    }
    if (bcur >= 0) {
        atomicAdd(&g_psum[bcur * HH2 + d], s);
        atomicMax(&g_pmax[bcur * HH2 + d], __float_as_int(m));
        if (d == 0) atomicAdd(&g_pcnt[bcur], (float)cl);
    }
}

// ---------------- head ----------------
__global__ void k_head(const float* __restrict__ fc1_w, const float* __restrict__ fc1_b,
                       const float* __restrict__ bn_g,  const float* __restrict__ bn_b,
                       const float* __restrict__ fc2_w, const float* __restrict__ fc2_b,
                       const float* __restrict__ dec1_w,const float* __restrict__ dec1_b,
                       const float* __restrict__ dec2_w,const float* __restrict__ dec2_b,
                       float* __restrict__ out) {
    __shared__ float sh[12288];
    float* g = sh;
    float* z = sh + 8192;
    int tid = threadIdx.x;

    for (int idx = tid; idx < BB * HH2; idx += 256) {
        int i = idx >> 7;
        float c = fmaxf(g_pcnt[i], 1.0f);
        g[idx] = g_psum[idx] / c + __int_as_float(g_pmax[idx]);
    }
    __syncthreads();
    for (int idx = tid; idx < BB * HH1; idx += 256) {
        int i = idx >> 6, j = idx & 63;
        float s = fc1_b[j];
        for (int k = 0; k < HH2; k++) s += g[i * HH2 + k] * fc1_w[k * HH1 + j];
        z[idx] = s;
    }
    __syncthreads();
    float* scale = sh + 5120;
    float* shift = sh + 5184;
    if (tid < HH1) {
        int j = tid;
        float mu = 0.f;
        for (int i = 0; i < BB; i++) mu += z[i * HH1 + j];
        mu *= (1.0f / BB);
        float var = 0.f;
        for (int i = 0; i < BB; i++) { float dv = z[i * HH1 + j] - mu; var += dv * dv; }
        var *= (1.0f / BB);
        float sc = bn_g[j] * rsqrtf(var + 1e-5f);
        scale[j] = sc;
        shift[j] = bn_b[j] - mu * sc;
    }
    __syncthreads();
    for (int idx = tid; idx < BB * HH1; idx += 256) {
        int j = idx & 63;
        float v = z[idx] * scale[j] + shift[j];
        z[idx] = (v > 0.f) ? v : 0.2f * v;
    }
    __syncthreads();
    float* emb = sh;
    for (int idx = tid; idx < BB * 16; idx += 256) {
        int i = idx >> 4, j = idx & 15;
        float s = fc2_b[j];
        for (int k = 0; k < HH1; k++) s += z[i * HH1 + k] * fc2_w[k * 16 + j];
        emb[idx] = s;
        out[BB * 32 + idx] = s;
    }
    __syncthreads();
    float* dd = sh + 1024;
    for (int idx = tid; idx < BB * HH1; idx += 256) {
        int i = idx >> 6, j = idx & 63;
        float s = dec1_b[j];
        for (int k = 0; k < 16; k++) s += emb[i * 16 + k] * dec1_w[k * HH1 + j];
        dd[idx] = (s > 0.f) ? s : 0.2f * s;
    }
    __syncthreads();
    for (int idx = tid; idx < BB * 32; idx += 256) {
        int i = idx >> 5, j = idx & 31;
        float s = dec2_b[j];
        for (int k = 0; k < HH1; k++) s += dd[i * HH1 + k] * dec2_w[k * 32 + j];
        out[idx] = s;
    }
}

// ---------------- launch ----------------
extern "C" void kernel_launch(void* const* d_in, const int* in_sizes, int n_in,
                              void* d_out, int out_size) {
    const float* x      = (const float*)d_in[0];
    const int*   ei     = (const int*)  d_in[1];
    const int*   et     = (const int*)  d_in[2];
    const int*   batch  = (const int*)  d_in[3];
    const float* W1     = (const float*)d_in[4];
    const float* root1  = (const float*)d_in[5];
    const float* b1     = (const float*)d_in[6];
    const float* W2     = (const float*)d_in[7];
    const float* root2  = (const float*)d_in[8];
    const float* b2     = (const float*)d_in[9];
    const float* fc1_w  = (const float*)d_in[10];
    const float* fc1_b  = (const float*)d_in[11];
    const float* bn_g   = (const float*)d_in[12];
    const float* bn_b   = (const float*)d_in[13];
    const float* fc2_w  = (const float*)d_in[14];
    const float* fc2_b  = (const float*)d_in[15];
    const float* dec1_w = (const float*)d_in[16];
    const float* dec1_b = (const float*)d_in[17];
    const float* dec2_w = (const float*)d_in[18];
    const float* dec2_b = (const float*)d_in[19];
    float* out = (float*)d_out;
    const int* src = ei;
    const int* dst = ei + EE;

    cudaFuncSetAttribute(k_gemm1_mma, cudaFuncAttributeMaxDynamicSharedMemorySize, G1_TOTAL);
    cudaFuncSetAttribute(k_gemm2_mma, cudaFuncAttributeMaxDynamicSharedMemorySize, G2_TOTAL);

    void *p_cnt, *p_s2, *p_psum, *p_pmax, *p_pcnt;
    cudaGetSymbolAddress(&p_cnt,  g_cnt);
    cudaGetSymbolAddress(&p_s2,   g_s2);
    cudaGetSymbolAddress(&p_psum, g_psum);
    cudaGetSymbolAddress(&p_pmax, g_pmax);
    cudaGetSymbolAddress(&p_pcnt, g_pcnt);

    cudaMemsetAsync(p_cnt,  0, (size_t)NSEG * 4);
    cudaMemsetAsync(p_s2,   0, (size_t)NN * 512 * 4);
    cudaMemsetAsync(p_psum, 0, BB * HH2 * 4);
    cudaMemsetAsync(p_pmax, 0, BB * HH2 * 4);
    cudaMemsetAsync(p_pcnt, 0, BB * 4);

    k_count<<<(EE + 255) / 256, 256>>>(dst, et);
    k_prep1<<<(PREP1_N + 255) / 256, 256>>>(W1, root1);
    k_prep2<<<(PREP2_N + 255) / 256, 256>>>(W2, root2);

    // layer 1: transform-first GEMM (77us) + ILP-8 atomic scatter
    k_gemm1_mma<<<(NN + 127) / 128, 128, G1_TOTAL>>>(x, b1);
    k_scatter1<<<(NGRP * 16 + 255) / 256, 256>>>(src, dst, et);

    // layer 2: ILP-8 aggregate-first scatter + wide-warp-tile GEMM
    k_scatter2<<<(NGRP * 16 + 255) / 256, 256>>>(src, dst, et);
    k_gemm2_mma<<<(NN + 127) / 128, 256, G2_TOTAL>>>(b2);

    k_pool<<<(NN + 31) / 32, 128>>>(batch);
    k_head<<<1, 256>>>(fc1_w, fc1_b, bn_g, bn_b, fc2_w, fc2_b,
                       dec1_w, dec1_b, dec2_w, dec2_b, out);
}

// round 16
// speedup vs baseline: 1.1579x; 1.1579x over previous
#include <cuda_runtime.h>
#include <cuda_bf16.h>
#include <cstdint>

#define NN  50000
#define EE  800000
#define RR  8
#define FIN 128
#define HH1 64
#define HH2 128
#define BB  64
#define NSEG (NN * RR)

// ---------------- device-global scratch ------------------------------------
__device__ __align__(16) float g_big[(size_t)NN * 512];  // h1 [n][8*64] fp32
__device__ __align__(16) float g_s2 [(size_t)NN * 512];  // S2 [n][8*64]
__device__ __align__(16) float g_x1[(size_t)NN * HH1];
__device__ __align__(16) float g_h2[(size_t)NN * HH2];
__device__ int   g_cnt[NSEG];
__device__ float g_psum[BB * HH2];
__device__ int   g_pmax[BB * HH2];
__device__ float g_pcnt[BB];
__device__ __align__(16) unsigned short Wb1h[9 * 64 * 128];   // [r][n][k]
__device__ __align__(16) unsigned short Wb1l[9 * 64 * 128];
__device__ __align__(16) unsigned short Wb2h[128 * 576];      // [n][k]
__device__ __align__(16) unsigned short Wb2l[128 * 576];

// ---------------- mma helpers ----------------
__device__ __forceinline__ uint32_t smem_u32(const void* p) {
    uint32_t a;
    asm("{ .reg .u64 t; cvta.to.shared.u64 t, %1; cvt.u32.u64 %0, t; }" : "=r"(a) : "l"(p));
    return a;
}
__device__ __forceinline__ void ldm_x4(uint32_t* r, uint32_t addr) {
    asm volatile("ldmatrix.sync.aligned.m8n8.x4.shared.b16 {%0,%1,%2,%3}, [%4];"
                 : "=r"(r[0]), "=r"(r[1]), "=r"(r[2]), "=r"(r[3]) : "r"(addr));
}
__device__ __forceinline__ void mma_bf16(float* c, const uint32_t* a, uint32_t b0, uint32_t b1) {
    asm volatile("mma.sync.aligned.m16n8k16.row.col.f32.bf16.bf16.f32 "
                 "{%0,%1,%2,%3}, {%4,%5,%6,%7}, {%8,%9}, {%0,%1,%2,%3};"
                 : "+f"(c[0]), "+f"(c[1]), "+f"(c[2]), "+f"(c[3])
                 : "r"(a[0]), "r"(a[1]), "r"(a[2]), "r"(a[3]), "r"(b0), "r"(b1));
}
__device__ __forceinline__ uint32_t pack_hi(float a, float b, uint32_t& lo) {
    __nv_bfloat16 ha = __float2bfloat16_rn(a), hb = __float2bfloat16_rn(b);
    __nv_bfloat16 la = __float2bfloat16_rn(a - __bfloat162float(ha));
    __nv_bfloat16 lb = __float2bfloat16_rn(b - __bfloat162float(hb));
    lo = (uint32_t)__bfloat16_as_ushort(la) | ((uint32_t)__bfloat16_as_ushort(lb) << 16);
    return (uint32_t)__bfloat16_as_ushort(ha) | ((uint32_t)__bfloat16_as_ushort(hb) << 16);
}

// ---------------- fused: degree count + both weight preps ------------------
#define PREP1_N (9 * 64 * 128)
#define PREP2_N (128 * 576)
#define PREP_TOTAL (EE + PREP1_N + PREP2_N)
__global__ void k_prep(const int* __restrict__ dst, const int* __restrict__ et,
                       const float* __restrict__ W1, const float* __restrict__ root1,
                       const float* __restrict__ W2, const float* __restrict__ root2) {
    int idx = blockIdx.x * blockDim.x + threadIdx.x;
    if (idx < EE) {
        atomicAdd(&g_cnt[dst[idx] * RR + et[idx]], 1);
    } else if (idx < EE + PREP1_N) {
        int i = idx - EE;
        int r = i >> 13, rem = i & 8191, n = rem >> 7, k = rem & 127;
        float v = (r < 8) ? W1[((size_t)r * 128 + k) * 64 + n] : root1[(size_t)k * 64 + n];
        __nv_bfloat16 h = __float2bfloat16_rn(v);
        Wb1h[i] = __bfloat16_as_ushort(h);
        Wb1l[i] = __bfloat16_as_ushort(__float2bfloat16_rn(v - __bfloat162float(h)));
    } else if (idx < PREP_TOTAL) {
        int j = idx - EE - PREP1_N;
        int n = j / 576, k = j % 576;
        float v = (k < 512) ? W2[(size_t)k * 128 + n] : root2[(size_t)(k - 512) * 128 + n];
        __nv_bfloat16 h = __float2bfloat16_rn(v);
        Wb2h[j] = __bfloat16_as_ushort(h);
        Wb2l[j] = __bfloat16_as_ushort(__float2bfloat16_rn(v - __bfloat162float(h)));
    }
}

// ---------------- layer-1 GEMM: 128 thr, block 128Mx64N, warp 64Mx32N ------
// (round-12/14 version, measured 77us)
#define G1_AL 32768
#define G1_BH 65536
#define G1_BL 81920
#define G1_TOTAL 98304

__global__ __launch_bounds__(128, 2) void k_gemm1_mma(const float* __restrict__ x,
                                                      const float* __restrict__ b1) {
    extern __shared__ char sm[];
    const int tid = threadIdx.x, lane = tid & 31, w = tid >> 5;
    const int n0 = blockIdx.x * 128;
    const int m_off = (w & 1) * 64;
    const int n_off = (w >> 1) * 32;
    const uint32_t sbase = smem_u32(sm);

    #pragma unroll
    for (int it = 0; it < 16; it++) {
        int idx = tid + it * 128;
        int row = idx >> 4, g = idx & 15;
        int n = n0 + row;
        float v[8];
        if (n < NN) {
            float4 a = *(const float4*)(x + (size_t)n * FIN + g * 8);
            float4 b = *(const float4*)(x + (size_t)n * FIN + g * 8 + 4);
            v[0]=a.x; v[1]=a.y; v[2]=a.z; v[3]=a.w; v[4]=b.x; v[5]=b.y; v[6]=b.z; v[7]=b.w;
        } else {
            #pragma unroll
            for (int j = 0; j < 8; j++) v[j] = 0.0f;
        }
        uint32_t hu[4], lu[4];
        #pragma unroll
        for (int m = 0; m < 4; m++) hu[m] = pack_hi(v[2*m], v[2*m+1], lu[m]);
        uint32_t off = row * 256 + ((g * 16) ^ ((row & 7) << 4));
        *(uint4*)(sm + off)         = make_uint4(hu[0], hu[1], hu[2], hu[3]);
        *(uint4*)(sm + G1_AL + off) = make_uint4(lu[0], lu[1], lu[2], lu[3]);
    }

    for (int r = 0; r < 9; r++) {
        #pragma unroll
        for (int it = 0; it < 8; it++) {
            int idx = tid + it * 128;
            int row = idx >> 4, g = idx & 15;
            uint4 hv = *(const uint4*)(Wb1h + ((size_t)r * 64 + row) * 128 + g * 8);
            uint4 lv = *(const uint4*)(Wb1l + ((size_t)r * 64 + row) * 128 + g * 8);
            uint32_t off = row * 256 + ((g * 16) ^ ((row & 7) << 4));
            *(uint4*)(sm + G1_BH + off) = hv;
            *(uint4*)(sm + G1_BL + off) = lv;
        }
        __syncthreads();

        float acc[4][4][4] = {};
        #pragma unroll
        for (int s = 0; s < 8; s++) {
            uint32_t ah[4][4], al[4][4];
            #pragma unroll
            for (int mt = 0; mt < 4; mt++) {
                int row = m_off + mt * 16 + (lane & 15);
                int kb = s * 32 + (lane >> 4) * 16;
                uint32_t off = row * 256 + (kb ^ ((row & 7) << 4));
                ldm_x4(ah[mt], sbase + off);
                ldm_x4(al[mt], sbase + G1_AL + off);
            }
            #pragma unroll
            for (int ng = 0; ng < 2; ng++) {
                uint32_t bh[4], bl[4];
                int nb = n_off + ng * 16 + (lane & 7) + ((lane >> 4) << 3);
                int kb = s * 32 + ((lane >> 3) & 1) * 16;
                uint32_t off = nb * 256 + (kb ^ ((nb & 7) << 4));
                ldm_x4(bh, sbase + G1_BH + off);
                ldm_x4(bl, sbase + G1_BL + off);
                #pragma unroll
                for (int mt = 0; mt < 4; mt++)
                    #pragma unroll
                    for (int sub = 0; sub < 2; sub++) {
                        float* c = acc[mt][ng * 2 + sub];
                        mma_bf16(c, ah[mt], bh[sub*2], bh[sub*2+1]);
                        mma_bf16(c, al[mt], bh[sub*2], bh[sub*2+1]);
                        mma_bf16(c, ah[mt], bl[sub*2], bl[sub*2+1]);
                    }
            }
        }

        int grow = lane >> 2, gcol = (lane & 3) * 2;
        #pragma unroll
        for (int mt = 0; mt < 4; mt++) {
            int nr0 = n0 + m_off + mt * 16 + grow;
            int nr1 = nr0 + 8;
            #pragma unroll
            for (int nt = 0; nt < 4; nt++) {
                int col = n_off + nt * 8 + gcol;
                float* c = acc[mt][nt];
                if (r < 8) {
                    if (nr0 < NN) *(float2*)&g_big[(size_t)nr0 * 512 + r * 64 + col] = make_float2(c[0], c[1]);
                    if (nr1 < NN) *(float2*)&g_big[(size_t)nr1 * 512 + r * 64 + col] = make_float2(c[2], c[3]);
                } else {
                    float bb0 = b1[col], bb1 = b1[col + 1];
                    if (nr0 < NN) *(float2*)&g_x1[(size_t)nr0 * 64 + col] = make_float2(c[0] + bb0, c[1] + bb1);
                    if (nr1 < NN) *(float2*)&g_x1[(size_t)nr1 * 64 + col] = make_float2(c[2] + bb0, c[3] + bb1);
                }
            }
        }
        __syncthreads();
    }
}

// ---------------- scatters: ILP=8 edges/thread, 16 thr/edge, vector red ----
#define NGRP (EE / 8)   // 100000 edge groups

__global__ __launch_bounds__(256) void k_scatter1(const int* __restrict__ src,
                                                  const int* __restrict__ dst,
                                                  const int* __restrict__ et) {
    long idx = (long)blockIdx.x * blockDim.x + threadIdx.x;
    int grp = (int)(idx >> 4);
    if (grp >= NGRP) return;
    int q = (int)(idx & 15);
    int e0 = grp * 8;
    int s[8], d[8], t[8];
    #pragma unroll
    for (int j = 0; j < 8; j++) { s[j] = src[e0+j]; d[j] = dst[e0+j]; t[j] = et[e0+j]; }
    int c[8];
    #pragma unroll
    for (int j = 0; j < 8; j++) c[j] = g_cnt[d[j] * RR + t[j]];
    float4 v[8];
    #pragma unroll
    for (int j = 0; j < 8; j++)
        v[j] = *(const float4*)&g_big[(size_t)s[j] * 512 + t[j] * 64 + q * 4];
    #pragma unroll
    for (int j = 0; j < 8; j++) {
        float w = 1.0f / (float)(c[j] > 1 ? c[j] : 1);
        float* p = &g_x1[(size_t)d[j] * 64 + q * 4];
        asm volatile("red.global.add.v4.f32 [%0], {%1, %2, %3, %4};"
                     :: "l"(p), "f"(w*v[j].x), "f"(w*v[j].y), "f"(w*v[j].z), "f"(w*v[j].w)
                     : "memory");
    }
}

__global__ __launch_bounds__(256) void k_scatter2(const int* __restrict__ src,
                                                  const int* __restrict__ dst,
                                                  const int* __restrict__ et) {
    long idx = (long)blockIdx.x * blockDim.x + threadIdx.x;
    int grp = (int)(idx >> 4);
    if (grp >= NGRP) return;
    int q = (int)(idx & 15);
    int e0 = grp * 8;
    int s[8], d[8], t[8];
    #pragma unroll
    for (int j = 0; j < 8; j++) { s[j] = src[e0+j]; d[j] = dst[e0+j]; t[j] = et[e0+j]; }
    int c[8];
    #pragma unroll
    for (int j = 0; j < 8; j++) c[j] = g_cnt[d[j] * RR + t[j]];
    float4 v[8];
    #pragma unroll
    for (int j = 0; j < 8; j++)
        v[j] = *(const float4*)&g_x1[(size_t)s[j] * 64 + q * 4];
    #pragma unroll
    for (int j = 0; j < 8; j++) {
        float w = 1.0f / (float)(c[j] > 1 ? c[j] : 1);
        float* p = &g_s2[(size_t)d[j] * 512 + t[j] * 64 + q * 4];
        asm volatile("red.global.add.v4.f32 [%0], {%1, %2, %3, %4};"
                     :: "l"(p), "f"(w*fmaxf(v[j].x,0.f)), "f"(w*fmaxf(v[j].y,0.f)),
                        "f"(w*fmaxf(v[j].z,0.f)), "f"(w*fmaxf(v[j].w,0.f)) : "memory");
    }
}

// ---------------- layer-2 GEMM: M-tile 64, 256 thr, 3 CTAs/SM --------------
// (round-11 version — empirical optimum for this K=576 shape)
#define G2_AL 8192
#define G2_BH 16384
#define G2_BL 32768
#define G2_TOTAL 49152

__global__ __launch_bounds__(256, 3) void k_gemm2_mma(const float* __restrict__ b2) {
    extern __shared__ char sm[];
    const int tid = threadIdx.x, lane = tid & 31, w = tid >> 5;
    const int n0 = blockIdx.x * 64;
    const int m_off = (w & 3) * 16;
    const int n_off = (w >> 2) * 64;
    const uint32_t sbase = smem_u32(sm);

    float acc[8][4] = {};

    for (int c = 0; c < 9; c++) {
        #pragma unroll
        for (int it = 0; it < 2; it++) {
            int idx = tid + it * 256;
            int row = idx >> 3, g = idx & 7;
            int n = n0 + row;
            float v[8];
            if (n < NN) {
                const float* pb = (c < 8) ? &g_s2[(size_t)n * 512 + c * 64 + g * 8]
                                          : &g_x1[(size_t)n * 64 + g * 8];
                float4 a = *(const float4*)pb;
                float4 b = *(const float4*)(pb + 4);
                if (c < 8) {
                    v[0]=a.x; v[1]=a.y; v[2]=a.z; v[3]=a.w; v[4]=b.x; v[5]=b.y; v[6]=b.z; v[7]=b.w;
                } else {
                    v[0]=fmaxf(a.x,0.f); v[1]=fmaxf(a.y,0.f); v[2]=fmaxf(a.z,0.f); v[3]=fmaxf(a.w,0.f);
                    v[4]=fmaxf(b.x,0.f); v[5]=fmaxf(b.y,0.f); v[6]=fmaxf(b.z,0.f); v[7]=fmaxf(b.w,0.f);
                }
            } else {
                #pragma unroll
                for (int j = 0; j < 8; j++) v[j] = 0.0f;
            }
            uint32_t hu[4], lu[4];
            #pragma unroll
            for (int m = 0; m < 4; m++) hu[m] = pack_hi(v[2*m], v[2*m+1], lu[m]);
            uint32_t off = row * 128 + ((g * 16) ^ ((row & 7) << 4));
            *(uint4*)(sm + off)         = make_uint4(hu[0], hu[1], hu[2], hu[3]);
            *(uint4*)(sm + G2_AL + off) = make_uint4(lu[0], lu[1], lu[2], lu[3]);
        }
        #pragma unroll
        for (int it = 0; it < 4; it++) {
            int idx = tid + it * 256;
            int row = idx >> 3, g = idx & 7;
            uint4 hv = *(const uint4*)(Wb2h + (size_t)row * 576 + c * 64 + g * 8);
            uint4 lv = *(const uint4*)(Wb2l + (size_t)row * 576 + c * 64 + g * 8);
            uint32_t off = row * 128 + ((g * 16) ^ ((row & 7) << 4));
            *(uint4*)(sm + G2_BH + off) = hv;
            *(uint4*)(sm + G2_BL + off) = lv;
        }
        __syncthreads();

        #pragma unroll
        for (int s = 0; s < 4; s++) {
            uint32_t ah[4], al[4];
            {
                int row = m_off + (lane & 15);
                int kb = s * 32 + (lane >> 4) * 16;
                uint32_t off = row * 128 + (kb ^ ((row & 7) << 4));
                ldm_x4(ah, sbase + off);
                ldm_x4(al, sbase + G2_AL + off);
            }
            #pragma unroll
            for (int ng = 0; ng < 4; ng++) {
                uint32_t bh[4], bl[4];
                int nb = n_off + ng * 16 + (lane & 7) + ((lane >> 4) << 3);
                int kb = s * 32 + ((lane >> 3) & 1) * 16;
                uint32_t off = nb * 128 + (kb ^ ((nb & 7) << 4));
                ldm_x4(bh, sbase + G2_BH + off);
                ldm_x4(bl, sbase + G2_BL + off);
                #pragma unroll
                for (int sub = 0; sub < 2; sub++) {
                    float* cc = acc[ng * 2 + sub];
                    mma_bf16(cc, ah, bh[sub*2], bh[sub*2+1]);
                    mma_bf16(cc, al, bh[sub*2], bh[sub*2+1]);
                    mma_bf16(cc, ah, bl[sub*2], bl[sub*2+1]);
                }
            }
        }
        __syncthreads();
    }

    int grow = lane >> 2, gcol = (lane & 3) * 2;
    int nr0 = n0 + m_off + grow;
    int nr1 = nr0 + 8;
    #pragma unroll
    for (int nt = 0; nt < 8; nt++) {
        int col = n_off + nt * 8 + gcol;
        float bb0 = b2[col], bb1 = b2[col + 1];
        float* cc = acc[nt];
        if (nr0 < NN)
            *(float2*)&g_h2[(size_t)nr0 * 128 + col] =
                make_float2(fmaxf(cc[0] + bb0, 0.f), fmaxf(cc[1] + bb1, 0.f));
        if (nr1 < NN)
            *(float2*)&g_h2[(size_t)nr1 * 128 + col] =
                make_float2(fmaxf(cc[2] + bb0, 0.f), fmaxf(cc[3] + bb1, 0.f));
    }
}

// ---------------- pooling ----------------
__global__ void k_pool(const int* __restrict__ batch) {
    __shared__ int sbt[32];
    int n0 = blockIdx.x * 32;
    int tid = threadIdx.x;
    if (tid < 32) sbt[tid] = (n0 + tid < NN) ? batch[n0 + tid] : -1;
    __syncthreads();
    int d = tid, bcur = -1, cl = 0;
    float s = 0.f, m = 0.f;
    for (int i = 0; i < 32; i++) {
        int n = n0 + i;
        if (n >= NN) break;
        int b = sbt[i];
        if (b != bcur) {
            if (bcur >= 0) {
                atomicAdd(&g_psum[bcur * HH2 + d], s);
                atomicMax(&g_pmax[bcur * HH2 + d], __float_as_int(m));
                if (d == 0) atomicAdd(&g_pcnt[bcur], (float)cl);
            }
            bcur = b; s = 0.f; m = 0.f; cl = 0;
        }
        float v = g_h2[(size_t)n * HH2 + d];
        s += v; m = fmaxf(m, v); cl++;
    }
    if (bcur >= 0) {
        atomicAdd(&g_psum[bcur * HH2 + d], s);
        atomicMax(&g_pmax[bcur * HH2 + d], __float_as_int(m));
        if (d == 0) atomicAdd(&g_pcnt[bcur], (float)cl);
    }
}

// ---------------- head ----------------
__global__ void k_head(const float* __restrict__ fc1_w, const float* __restrict__ fc1_b,
                       const float* __restrict__ bn_g,  const float* __restrict__ bn_b,
                       const float* __restrict__ fc2_w, const float* __restrict__ fc2_b,
                       const float* __restrict__ dec1_w,const float* __restrict__ dec1_b,
                       const float* __restrict__ dec2_w,const float* __restrict__ dec2_b,
                       float* __restrict__ out) {
    __shared__ float sh[12288];
    float* g = sh;
    float* z = sh + 8192;
    int tid = threadIdx.x;

    for (int idx = tid; idx < BB * HH2; idx += 256) {
        int i = idx >> 7;
        float c = fmaxf(g_pcnt[i], 1.0f);
        g[idx] = g_psum[idx] / c + __int_as_float(g_pmax[idx]);
    }
    __syncthreads();
    for (int idx = tid; idx < BB * HH1; idx += 256) {
        int i = idx >> 6, j = idx & 63;
        float s = fc1_b[j];
        for (int k = 0; k < HH2; k++) s += g[i * HH2 + k] * fc1_w[k * HH1 + j];
        z[idx] = s;
    }
    __syncthreads();
    float* scale = sh + 5120;
    float* shift = sh + 5184;
    if (tid < HH1) {
        int j = tid;
        float mu = 0.f;
        for (int i = 0; i < BB; i++) mu += z[i * HH1 + j];
        mu *= (1.0f / BB);
        float var = 0.f;
        for (int i = 0; i < BB; i++) { float dv = z[i * HH1 + j] - mu; var += dv * dv; }
        var *= (1.0f / BB);
        float sc = bn_g[j] * rsqrtf(var + 1e-5f);
        scale[j] = sc;
        shift[j] = bn_b[j] - mu * sc;
    }
    __syncthreads();
    for (int idx = tid; idx < BB * HH1; idx += 256) {
        int j = idx & 63;
        float v = z[idx] * scale[j] + shift[j];
        z[idx] = (v > 0.f) ? v : 0.2f * v;
    }
    __syncthreads();
    float* emb = sh;
    for (int idx = tid; idx < BB * 16; idx += 256) {
        int i = idx >> 4, j = idx & 15;
        float s = fc2_b[j];
        for (int k = 0; k < HH1; k++) s += z[i * HH1 + k] * fc2_w[k * 16 + j];
        emb[idx] = s;
        out[BB * 32 + idx] = s;
    }
    __syncthreads();
    float* dd = sh + 1024;
    for (int idx = tid; idx < BB * HH1; idx += 256) {
        int i = idx >> 6, j = idx & 63;
        float s = dec1_b[j];
        for (int k = 0; k < 16; k++) s += emb[i * 16 + k] * dec1_w[k * HH1 + j];
        dd[idx] = (s > 0.f) ? s : 0.2f * s;
    }
    __syncthreads();
    for (int idx = tid; idx < BB * 32; idx += 256) {
        int i = idx >> 5, j = idx & 31;
        float s = dec2_b[j];
        for (int k = 0; k < HH1; k++) s += dd[i * HH1 + k] * dec2_w[k * 32 + j];
        out[idx] = s;
    }
}

// ---------------- launch ----------------
extern "C" void kernel_launch(void* const* d_in, const int* in_sizes, int n_in,
                              void* d_out, int out_size) {
    const float* x      = (const float*)d_in[0];
    const int*   ei     = (const int*)  d_in[1];
    const int*   et     = (const int*)  d_in[2];
    const int*   batch  = (const int*)  d_in[3];
    const float* W1     = (const float*)d_in[4];
    const float* root1  = (const float*)d_in[5];
    const float* b1     = (const float*)d_in[6];
    const float* W2     = (const float*)d_in[7];
    const float* root2  = (const float*)d_in[8];
    const float* b2     = (const float*)d_in[9];
    const float* fc1_w  = (const float*)d_in[10];
    const float* fc1_b  = (const float*)d_in[11];
    const float* bn_g   = (const float*)d_in[12];
    const float* bn_b   = (const float*)d_in[13];
    const float* fc2_w  = (const float*)d_in[14];
    const float* fc2_b  = (const float*)d_in[15];
    const float* dec1_w = (const float*)d_in[16];
    const float* dec1_b = (const float*)d_in[17];
    const float* dec2_w = (const float*)d_in[18];
    const float* dec2_b = (const float*)d_in[19];
    float* out = (float*)d_out;
    const int* src = ei;
    const int* dst = ei + EE;

    cudaFuncSetAttribute(k_gemm1_mma, cudaFuncAttributeMaxDynamicSharedMemorySize, G1_TOTAL);
    cudaFuncSetAttribute(k_gemm2_mma, cudaFuncAttributeMaxDynamicSharedMemorySize, G2_TOTAL);

    void *p_cnt, *p_s2, *p_psum, *p_pmax, *p_pcnt;
    cudaGetSymbolAddress(&p_cnt,  g_cnt);
    cudaGetSymbolAddress(&p_s2,   g_s2);
    cudaGetSymbolAddress(&p_psum, g_psum);
    cudaGetSymbolAddress(&p_pmax, g_pmax);
    cudaGetSymbolAddress(&p_pcnt, g_pcnt);

    cudaMemsetAsync(p_cnt,  0, (size_t)NSEG * 4);
    cudaMemsetAsync(p_s2,   0, (size_t)NN * 512 * 4);
    cudaMemsetAsync(p_psum, 0, BB * HH2 * 4);
    cudaMemsetAsync(p_pmax, 0, BB * HH2 * 4);
    cudaMemsetAsync(p_pcnt, 0, BB * 4);

    // fused: degree count + both weight preps (one launch)
    k_prep<<<(PREP_TOTAL + 255) / 256, 256>>>(dst, et, W1, root1, W2, root2);

    // layer 1: transform-first GEMM (77us) + ILP-8 atomic scatter
    k_gemm1_mma<<<(NN + 127) / 128, 128, G1_TOTAL>>>(x, b1);
    k_scatter1<<<(NGRP * 16 + 255) / 256, 256>>>(src, dst, et);

    // layer 2: ILP-8 aggregate-first scatter + fused GEMM (round-11 shape)
    k_scatter2<<<(NGRP * 16 + 255) / 256, 256>>>(src, dst, et);
    k_gemm2_mma<<<(NN + 63) / 64, 256, G2_TOTAL>>>(b2);

    k_pool<<<(NN + 31) / 32, 128>>>(batch);
    k_head<<<1, 256>>>(fc1_w, fc1_b, bn_g, bn_b, fc2_w, fc2_b,
                       dec1_w, dec1_b, dec2_w, dec2_b, out);
}